// round 1
// baseline (speedup 1.0000x reference)
#include <cuda_runtime.h>
#include <math.h>

#define Bb 4
#define Ss 2048
#define Dd 768
#define BS (Bb*Ss)
#define SSQ ((size_t)Ss*(size_t)Ss)

// -------- scratch (static device globals; no runtime allocation) --------
static __device__ float g_h[(size_t)BS*Dd];   // layernorm output
static __device__ float g_Y[(size_t)BS*Dd];   // Y = H * M^T
static __device__ float g_M[Dd*Dd];           // M = Wq * Wk^T
static __device__ float g_v1[Dd];
static __device__ float g_v2[Dd];
static __device__ float g_c0;
static __device__ float g_du[BS], g_dd[BS], g_a1v[BS], g_a2v[BS];
static __device__ float g_su[BS], g_sd[BS];
static __device__ float g_nsup[BS], g_nsub[BS], g_Lg[BS];
static __device__ float g_P[BS];

__device__ __forceinline__ float warp_sum(float v){
#pragma unroll
    for (int o = 16; o; o >>= 1) v += __shfl_xor_sync(0xffffffffu, v, o);
    return v;
}

// ---------------- LayerNorm: one block (256 thr) per row ----------------
__global__ __launch_bounds__(256) void ln_kernel(const float* __restrict__ x,
                                                 const float* __restrict__ w,
                                                 const float* __restrict__ b){
    int row = blockIdx.x;
    const float* xr = x + (size_t)row * Dd;
    int t = threadIdx.x;
    float v0 = xr[t], v1 = xr[t+256], v2 = xr[t+512];
    float s = v0 + v1 + v2;
    float q = v0*v0 + v1*v1 + v2*v2;
    __shared__ float rs[8], rq[8];
    s = warp_sum(s); q = warp_sum(q);
    if ((t & 31) == 0){ rs[t>>5] = s; rq[t>>5] = q; }
    __syncthreads();
    if (t < 32){
        float a = (t < 8) ? rs[t] : 0.f;
        float c = (t < 8) ? rq[t] : 0.f;
#pragma unroll
        for (int o = 4; o; o >>= 1){
            a += __shfl_xor_sync(0xffffffffu, a, o);
            c += __shfl_xor_sync(0xffffffffu, c, o);
        }
        if (t == 0){ rs[0] = a; rq[0] = c; }
    }
    __syncthreads();
    float mu   = rs[0] * (1.f/Dd);
    float var  = fmaxf(rq[0] * (1.f/Dd) - mu*mu, 0.f);
    float rstd = rsqrtf(var + 1e-12f);
    float* hr = g_h + (size_t)row * Dd;
    hr[t]     = (v0 - mu) * rstd * w[t]     + b[t];
    hr[t+256] = (v1 - mu) * rstd * w[t+256] + b[t+256];
    hr[t+512] = (v2 - mu) * rstd * w[t+512] + b[t+512];
}

// ---------------- NT GEMM: C[M,N] = A[M,K] * B[N,K]^T ----------------
// 128x128 tile, BK=16, 256 threads, 8x8 microtile. M,N multiples of 128, K of 16.
__device__ __forceinline__ void gemm_nt_body(const float* __restrict__ A,
                                             const float* __restrict__ Bm,
                                             float* __restrict__ C,
                                             int M, int N, int K){
    __shared__ float As[16][128];
    __shared__ float Bs[16][128];
    int bm = blockIdx.y * 128, bn = blockIdx.x * 128;
    int tid = threadIdx.x;
    int tx = tid & 15, ty = tid >> 4;
    float acc[8][8];
#pragma unroll
    for (int i = 0; i < 8; i++)
#pragma unroll
        for (int j = 0; j < 8; j++) acc[i][j] = 0.f;

    for (int k0 = 0; k0 < K; k0 += 16){
#pragma unroll
        for (int l = 0; l < 2; l++){
            int f = tid + l*256;
            int row = f >> 2, kq = f & 3;
            float4 v = *(const float4*)(A  + (size_t)(bm+row)*K + k0 + kq*4);
            As[kq*4+0][row]=v.x; As[kq*4+1][row]=v.y; As[kq*4+2][row]=v.z; As[kq*4+3][row]=v.w;
            float4 u = *(const float4*)(Bm + (size_t)(bn+row)*K + k0 + kq*4);
            Bs[kq*4+0][row]=u.x; Bs[kq*4+1][row]=u.y; Bs[kq*4+2][row]=u.z; Bs[kq*4+3][row]=u.w;
        }
        __syncthreads();
#pragma unroll
        for (int kk = 0; kk < 16; kk++){
            float4 a0 = *(const float4*)&As[kk][ty*8];
            float4 a1 = *(const float4*)&As[kk][ty*8+4];
            float4 b0 = *(const float4*)&Bs[kk][tx*8];
            float4 b1 = *(const float4*)&Bs[kk][tx*8+4];
            float av[8] = {a0.x,a0.y,a0.z,a0.w,a1.x,a1.y,a1.z,a1.w};
            float bv[8] = {b0.x,b0.y,b0.z,b0.w,b1.x,b1.y,b1.z,b1.w};
#pragma unroll
            for (int i = 0; i < 8; i++)
#pragma unroll
                for (int j = 0; j < 8; j++)
                    acc[i][j] = fmaf(av[i], bv[j], acc[i][j]);
        }
        __syncthreads();
    }
#pragma unroll
    for (int i = 0; i < 8; i++){
        int r = bm + ty*8 + i;
        float* cp = C + (size_t)r*N + bn + tx*8;
        *(float4*)cp     = make_float4(acc[i][0],acc[i][1],acc[i][2],acc[i][3]);
        *(float4*)(cp+4) = make_float4(acc[i][4],acc[i][5],acc[i][6],acc[i][7]);
    }
}

__global__ __launch_bounds__(256) void gemm_M_kernel(const float* __restrict__ wq,
                                                     const float* __restrict__ wk){
    gemm_nt_body(wq, wk, g_M, Dd, Dd, Dd);        // M[d,e] = sum_i wq[d,i]*wk[e,i]
}
__global__ __launch_bounds__(256) void gemm_Y_kernel(){
    gemm_nt_body(g_h, g_M, g_Y, BS, Dd, Dd);       // Y[t,d] = sum_e h[t,e]*M[d,e]
}

// ---------------- bias vectors: v1 = Wq*bk, v2 = Wk*bq, c0 = bq.bk ----------------
__global__ __launch_bounds__(256) void biasvec_kernel(const float* __restrict__ wq,
                                                      const float* __restrict__ wk,
                                                      const float* __restrict__ bq,
                                                      const float* __restrict__ bk){
    int wid  = (blockIdx.x*256 + threadIdx.x) >> 5;
    int lane = threadIdx.x & 31;
    if (wid < Dd){
        const float* r = wq + (size_t)wid * Dd;
        float a = 0.f;
        for (int j = lane; j < Dd; j += 32) a += r[j] * bk[j];
        a = warp_sum(a);
        if (!lane) g_v1[wid] = a;
    } else if (wid < 2*Dd){
        int d2 = wid - Dd;
        const float* r = wk + (size_t)d2 * Dd;
        float a = 0.f;
        for (int j = lane; j < Dd; j += 32) a += r[j] * bq[j];
        a = warp_sum(a);
        if (!lane) g_v2[d2] = a;
    } else if (wid == 2*Dd){
        float a = 0.f;
        for (int j = lane; j < Dd; j += 32) a += bq[j] * bk[j];
        a = warp_sum(a);
        if (!lane) g_c0 = a;
    }
}

// ---------------- band dot products: one warp per (b,s) row ----------------
__global__ __launch_bounds__(256) void band_dots_kernel(){
    int wid  = (blockIdx.x*256 + threadIdx.x) >> 5;
    int lane = threadIdx.x & 31;
    if (wid >= BS) return;
    int s = wid & (Ss-1);
    const float* h  = g_h + (size_t)wid * Dd;
    const float* yu = g_Y + (size_t)(wid+1) * Dd;
    const float* yd = g_Y + (size_t)(wid-1) * Dd;
    bool hasU = (s < Ss-1), hasD = (s > 0);
    float au=0.f, ad=0.f, a1=0.f, a2=0.f;
#pragma unroll
    for (int j = lane*4; j < Dd; j += 128){
        float4 hv = *(const float4*)(h + j);
        float4 w1 = *(const float4*)(g_v1 + j);
        float4 w2 = *(const float4*)(g_v2 + j);
        a1 += hv.x*w1.x + hv.y*w1.y + hv.z*w1.z + hv.w*w1.w;
        a2 += hv.x*w2.x + hv.y*w2.y + hv.z*w2.z + hv.w*w2.w;
        if (hasU){ float4 y = *(const float4*)(yu + j);
                   au += hv.x*y.x + hv.y*y.y + hv.z*y.z + hv.w*y.w; }
        if (hasD){ float4 y = *(const float4*)(yd + j);
                   ad += hv.x*y.x + hv.y*y.y + hv.z*y.z + hv.w*y.w; }
    }
    au = warp_sum(au); ad = warp_sum(ad); a1 = warp_sum(a1); a2 = warp_sum(a2);
    if (lane == 0){ g_du[wid]=au; g_dd[wid]=ad; g_a1v[wid]=a1; g_a2v[wid]=a2; }
}

// ---------------- banded softmax (<=2 entries per row) ----------------
__global__ __launch_bounds__(256) void band_softmax_kernel(const int* __restrict__ am){
    int row = blockIdx.x*256 + threadIdx.x;
    if (row >= BS) return;
    int b = row >> 11, s = row & (Ss-1);
    const int* amr = am + (size_t)b*SSQ + (size_t)s*Ss;
    bool au = (s < Ss-1) && ((amr[s+1] & 1) != 0);
    bool ad = (s > 0)    && ((amr[s-1] & 1) != 0);
    float su = 0.f, sd = 0.f;
    if (au || ad){
        float c0 = g_c0;
        const float NEG = -3.0e38f;
        float eu = au ? (g_du[row] + g_a1v[row] + g_a2v[row+1] + c0) * (1.f/Dd) : NEG;
        float ed = ad ? (g_dd[row] + g_a1v[row] + g_a2v[row-1] + c0) * (1.f/Dd) : NEG;
        float m  = fmaxf(eu, ed);
        float xu = au ? __expf(eu - m) : 0.f;
        float xd = ad ? __expf(ed - m) : 0.f;
        float inv = 1.f / (xu + xd);
        su = xu * inv; sd = xd * inv;
    }
    g_su[row] = su; g_sd[row] = sd;
}

// ---------------- band n values + L = log(n_superdiag + 1e-9) ----------------
__global__ __launch_bounds__(256) void band_n_kernel(const float* __restrict__ prior){
    int row = blockIdx.x*256 + threadIdx.x;
    if (row >= BS) return;
    int b = row >> 11, s = row & (Ss-1);
    if (s == Ss-1){ g_Lg[row] = 0.f; return; }
    float p  = g_su[row] * g_sd[row+1];   // softn[s,s+1] * softn[s+1,s]
    float nv = sqrtf(p + 1e-9f);
    size_t base = (size_t)b*SSQ + (size_t)s*Ss;
    float p1 = prior[base + s + 1];
    float p2 = prior[base + Ss + s];
    float nsup = p1 + (1.f - p1) * nv;
    float nsub = p2 + (1.f - p2) * nv;
    g_nsup[row] = nsup; g_nsub[row] = nsub;
    g_Lg[row] = logf(nsup + 1e-9f);
}

// ---------------- exclusive prefix sum of L per batch ----------------
__global__ __launch_bounds__(1024) void scan_kernel(){
    __shared__ float bufA[Ss], bufB[Ss];
    int b = blockIdx.x;
    float* in = bufA; float* out = bufB;
    for (int i = threadIdx.x; i < Ss; i += 1024) in[i] = g_Lg[b*Ss + i];
    __syncthreads();
    for (int off = 1; off < Ss; off <<= 1){
        for (int i = threadIdx.x; i < Ss; i += 1024)
            out[i] = (i >= off) ? (in[i] + in[i-off]) : in[i];
        __syncthreads();
        float* t = in; in = out; out = t;
    }
    for (int i = threadIdx.x; i < Ss; i += 1024)
        g_P[b*Ss + i] = (i == 0) ? 0.f : in[i-1];
}

// ---------------- dense pass: write full g and n ----------------
__global__ __launch_bounds__(256) void dense_kernel(const float* __restrict__ prior,
                                                    float* __restrict__ gO,
                                                    float* __restrict__ nO){
    __shared__ float sP[Ss];
    int b  = blockIdx.x >> 8;          // 256 blocks per batch
    int r0 = (blockIdx.x & 255) * 8;   // 8 rows per block
    const float* Pb = g_P + b*Ss;
    for (int i = threadIdx.x; i < Ss; i += 256) sP[i] = Pb[i];
    __syncthreads();
    const float CC  = 3.16227766016838e-5f;  // sqrt(1e-9)
    const float OMC = 1.f - CC;
    size_t bbase = (size_t)b * SSQ;
#pragma unroll
    for (int r = 0; r < 8; r++){
        int i = r0 + r;
        float Pi = sP[i];
        size_t rbase = bbase + (size_t)i*Ss;
#pragma unroll
        for (int ccI = 0; ccI < 2; ccI++){
            int c  = threadIdx.x + ccI*256;
            int k0 = c * 4;
            float4 pr = *(const float4*)(prior + rbase + k0);
            float4 pk = *(const float4*)(sP + k0);
            float4 nv;
            nv.x = fmaf(pr.x, OMC, CC);
            nv.y = fmaf(pr.y, OMC, CC);
            nv.z = fmaf(pr.z, OMC, CC);
            nv.w = fmaf(pr.w, OMC, CC);
            float dx = (k0+0 > i) ? pk.x - Pi : Pi - pk.x;
            float dy = (k0+1 > i) ? pk.y - Pi : Pi - pk.y;
            float dz = (k0+2 > i) ? pk.z - Pi : Pi - pk.z;
            float dw = (k0+3 > i) ? pk.w - Pi : Pi - pk.w;
            float dm = fmaxf(fmaxf(dx,dy), fmaxf(dz,dw));
            float4 gv;
            if (__ballot_sync(0xffffffffu, dm > -30.f)){   // warp-uniform exp skip
                gv.x = __expf(dx) + 1e-9f;
                gv.y = __expf(dy) + 1e-9f;
                gv.z = __expf(dz) + 1e-9f;
                gv.w = __expf(dw) + 1e-9f;
            } else {
                gv.x = gv.y = gv.z = gv.w = 1e-9f;
            }
            *(float4*)(nO + rbase + k0) = nv;
            *(float4*)(gO + rbase + k0) = gv;
        }
    }
}

// ---------------- patch band n entries and g diagonal ----------------
__global__ __launch_bounds__(256) void patch_kernel(const float* __restrict__ prior,
                                                    float* __restrict__ gO,
                                                    float* __restrict__ nO){
    int row = blockIdx.x*256 + threadIdx.x;
    if (row >= BS) return;
    int b = row >> 11, s = row & (Ss-1);
    const float CC = 3.16227766016838e-5f;
    size_t bbase = (size_t)b * SSQ;
    float pd = prior[bbase + (size_t)s*Ss + s];
    gO[bbase + (size_t)s*Ss + s] = fmaf(pd, 1.f - CC, CC);   // g[i,i] = n[i,i]
    if (s < Ss-1){
        nO[bbase + (size_t)s*Ss + s + 1]   = g_nsup[row];
        nO[bbase + (size_t)(s+1)*Ss + s]   = g_nsub[row];
    }
}

// ---------------- launch ----------------
extern "C" void kernel_launch(void* const* d_in, const int* in_sizes, int n_in,
                              void* d_out, int out_size){
    const float* hidden = (const float*)d_in[0];
    const int*   amask  = (const int*)  d_in[1];
    const float* prior  = (const float*)d_in[2];
    const float* lnw    = (const float*)d_in[3];
    const float* lnb    = (const float*)d_in[4];
    const float* wq     = (const float*)d_in[5];
    const float* bq     = (const float*)d_in[6];
    const float* wk     = (const float*)d_in[7];
    const float* bk     = (const float*)d_in[8];
    float* gO = (float*)d_out;
    float* nO = gO + (size_t)Bb * SSQ;

    ln_kernel<<<BS, 256>>>(hidden, lnw, lnb);
    gemm_M_kernel<<<dim3(Dd/128, Dd/128), 256>>>(wq, wk);
    biasvec_kernel<<<193, 256>>>(wq, wk, bq, bk);
    gemm_Y_kernel<<<dim3(Dd/128, BS/128), 256>>>();
    band_dots_kernel<<<BS/8, 256>>>();
    band_softmax_kernel<<<BS/256, 256>>>(amask);
    band_n_kernel<<<BS/256, 256>>>(prior);
    scan_kernel<<<Bb, 1024>>>();
    dense_kernel<<<Bb*(Ss/8), 256>>>(prior, gO, nO);
    patch_kernel<<<BS/256, 256>>>(prior, gO, nO);
}

// round 2
// speedup vs baseline: 2.1424x; 2.1424x over previous
#include <cuda_runtime.h>
#include <math.h>
#include <stdint.h>

#define Bb 4
#define Ss 2048
#define Dd 768
#define BS (Bb*Ss)
#define SSQ ((size_t)Ss*(size_t)Ss)

// -------- scratch (static device globals; no runtime allocation) --------
static __device__ float g_h[(size_t)BS*Dd];   // layernorm output
static __device__ float g_Y[(size_t)BS*Dd];   // Y = H * M^T
static __device__ float g_M[Dd*Dd];           // M = Wq * Wk^T
static __device__ float g_v1[Dd];
static __device__ float g_v2[Dd];
static __device__ float g_c0;
static __device__ float g_du[BS], g_dd[BS], g_a1v[BS], g_a2v[BS];
static __device__ float g_nsup[BS], g_nsub[BS], g_Lg[BS];
static __device__ float g_P[BS];

__device__ __forceinline__ float warp_sum(float v){
#pragma unroll
    for (int o = 16; o; o >>= 1) v += __shfl_xor_sync(0xffffffffu, v, o);
    return v;
}

// ---------------- LayerNorm: one block (256 thr) per row ----------------
__global__ __launch_bounds__(256) void ln_kernel(const float* __restrict__ x,
                                                 const float* __restrict__ w,
                                                 const float* __restrict__ b){
    int row = blockIdx.x;
    const float* xr = x + (size_t)row * Dd;
    int t = threadIdx.x;
    float v0 = xr[t], v1 = xr[t+256], v2 = xr[t+512];
    float s = v0 + v1 + v2;
    float q = v0*v0 + v1*v1 + v2*v2;
    __shared__ float rs[8], rq[8];
    s = warp_sum(s); q = warp_sum(q);
    if ((t & 31) == 0){ rs[t>>5] = s; rq[t>>5] = q; }
    __syncthreads();
    if (t < 32){
        float a = (t < 8) ? rs[t] : 0.f;
        float c = (t < 8) ? rq[t] : 0.f;
#pragma unroll
        for (int o = 4; o; o >>= 1){
            a += __shfl_xor_sync(0xffffffffu, a, o);
            c += __shfl_xor_sync(0xffffffffu, c, o);
        }
        if (t == 0){ rs[0] = a; rq[0] = c; }
    }
    __syncthreads();
    float mu   = rs[0] * (1.f/Dd);
    float var  = fmaxf(rq[0] * (1.f/Dd) - mu*mu, 0.f);
    float rstd = rsqrtf(var + 1e-12f);
    float* hr = g_h + (size_t)row * Dd;
    hr[t]     = (v0 - mu) * rstd * w[t]     + b[t];
    hr[t+256] = (v1 - mu) * rstd * w[t+256] + b[t+256];
    hr[t+512] = (v2 - mu) * rstd * w[t+512] + b[t+512];
}

// ================= tf32 tensor-core NT GEMM: C = A(MxK) * B(NxK)^T =================
__device__ __forceinline__ uint32_t f2tf32(float x){
    uint32_t r; asm("cvt.rna.tf32.f32 %0, %1;" : "=r"(r) : "f"(x)); return r;
}
__device__ __forceinline__ void cp16(uint32_t dst, const void* src){
    asm volatile("cp.async.ca.shared.global [%0], [%1], 16;" :: "r"(dst), "l"(src));
}

__device__ __forceinline__ void gemm_nt_tf32_body(const float* __restrict__ A,
                                                  const float* __restrict__ B,
                                                  float* __restrict__ C,
                                                  int M, int N, int K){
    __shared__ __align__(16) float As[2][128][20];
    __shared__ __align__(16) float Bs[2][128][20];
    const int tid = threadIdx.x;
    const int bm = blockIdx.y * 128, bn = blockIdx.x * 128;
    const int wid = tid >> 5, lane = tid & 31;
    const int wm = (wid >> 2) * 64, wn = (wid & 3) * 32;   // 2x4 warp grid
    const int g = lane >> 2, qc = lane & 3;
    const int lrow = tid >> 2, lkq = tid & 3;

    const float* Ap0 = A + (size_t)(bm + lrow)      * K + lkq*4;
    const float* Ap1 = A + (size_t)(bm + lrow + 64) * K + lkq*4;
    const float* Bp0 = B + (size_t)(bn + lrow)      * K + lkq*4;
    const float* Bp1 = B + (size_t)(bn + lrow + 64) * K + lkq*4;
    uint32_t sa0[2], sa1[2], sb0[2], sb1[2];
#pragma unroll
    for (int s = 0; s < 2; s++){
        sa0[s] = (uint32_t)__cvta_generic_to_shared(&As[s][lrow][lkq*4]);
        sa1[s] = (uint32_t)__cvta_generic_to_shared(&As[s][lrow+64][lkq*4]);
        sb0[s] = (uint32_t)__cvta_generic_to_shared(&Bs[s][lrow][lkq*4]);
        sb1[s] = (uint32_t)__cvta_generic_to_shared(&Bs[s][lrow+64][lkq*4]);
    }

    float acc[4][4][4];
#pragma unroll
    for (int i = 0; i < 4; i++)
#pragma unroll
        for (int j = 0; j < 4; j++)
#pragma unroll
            for (int k = 0; k < 4; k++) acc[i][j][k] = 0.f;

    const int niter = K / 16;
    cp16(sa0[0], Ap0); cp16(sa1[0], Ap1); cp16(sb0[0], Bp0); cp16(sb1[0], Bp1);
    asm volatile("cp.async.commit_group;");

    for (int it = 0; it < niter; it++){
        const int st = it & 1;
        if (it + 1 < niter){
            const int k0 = (it + 1) * 16;
            cp16(sa0[st^1], Ap0 + k0); cp16(sa1[st^1], Ap1 + k0);
            cp16(sb0[st^1], Bp0 + k0); cp16(sb1[st^1], Bp1 + k0);
            asm volatile("cp.async.commit_group;");
            asm volatile("cp.async.wait_group 1;");
        } else {
            asm volatile("cp.async.wait_group 0;");
        }
        __syncthreads();
#pragma unroll
        for (int ks = 0; ks < 2; ks++){
            const int kk = ks * 8;
            uint32_t af[4][4], bf[4][2];
#pragma unroll
            for (int tm = 0; tm < 4; tm++){
                int r0 = wm + tm*16 + g;
                af[tm][0] = f2tf32(As[st][r0  ][kk+qc  ]);
                af[tm][1] = f2tf32(As[st][r0+8][kk+qc  ]);
                af[tm][2] = f2tf32(As[st][r0  ][kk+qc+4]);
                af[tm][3] = f2tf32(As[st][r0+8][kk+qc+4]);
            }
#pragma unroll
            for (int tn = 0; tn < 4; tn++){
                int n0 = wn + tn*8 + g;
                bf[tn][0] = f2tf32(Bs[st][n0][kk+qc  ]);
                bf[tn][1] = f2tf32(Bs[st][n0][kk+qc+4]);
            }
#pragma unroll
            for (int tm = 0; tm < 4; tm++)
#pragma unroll
                for (int tn = 0; tn < 4; tn++)
                    asm volatile(
                        "mma.sync.aligned.m16n8k8.row.col.f32.tf32.tf32.f32 "
                        "{%0,%1,%2,%3},{%4,%5,%6,%7},{%8,%9},{%0,%1,%2,%3};"
                        : "+f"(acc[tm][tn][0]), "+f"(acc[tm][tn][1]),
                          "+f"(acc[tm][tn][2]), "+f"(acc[tm][tn][3])
                        : "r"(af[tm][0]), "r"(af[tm][1]), "r"(af[tm][2]), "r"(af[tm][3]),
                          "r"(bf[tn][0]), "r"(bf[tn][1]));
        }
        __syncthreads();
    }

#pragma unroll
    for (int tm = 0; tm < 4; tm++){
        int r = bm + wm + tm*16 + g;
#pragma unroll
        for (int tn = 0; tn < 4; tn++){
            int cc = bn + wn + tn*8 + qc*2;
            *(float2*)&C[(size_t)r*N + cc]     = make_float2(acc[tm][tn][0], acc[tm][tn][1]);
            *(float2*)&C[(size_t)(r+8)*N + cc] = make_float2(acc[tm][tn][2], acc[tm][tn][3]);
        }
    }
}

__global__ __launch_bounds__(256) void gemm_M_kernel(const float* __restrict__ wq,
                                                     const float* __restrict__ wk){
    gemm_nt_tf32_body(wq, wk, g_M, Dd, Dd, Dd);   // M[d,e] = sum_i wq[d,i]*wk[e,i]
}
__global__ __launch_bounds__(256) void gemm_Y_kernel(){
    gemm_nt_tf32_body(g_h, g_M, g_Y, BS, Dd, Dd); // Y[t,d] = sum_e h[t,e]*M[d,e]
}

// ---------------- bias vectors: v1 = Wq*bk, v2 = Wk*bq, c0 = bq.bk ----------------
__global__ __launch_bounds__(256) void biasvec_kernel(const float* __restrict__ wq,
                                                      const float* __restrict__ wk,
                                                      const float* __restrict__ bq,
                                                      const float* __restrict__ bk){
    int wid  = (blockIdx.x*256 + threadIdx.x) >> 5;
    int lane = threadIdx.x & 31;
    if (wid < Dd){
        const float* r = wq + (size_t)wid * Dd;
        float a = 0.f;
        for (int j = lane; j < Dd; j += 32) a += r[j] * bk[j];
        a = warp_sum(a);
        if (!lane) g_v1[wid] = a;
    } else if (wid < 2*Dd){
        int d2 = wid - Dd;
        const float* r = wk + (size_t)d2 * Dd;
        float a = 0.f;
        for (int j = lane; j < Dd; j += 32) a += r[j] * bq[j];
        a = warp_sum(a);
        if (!lane) g_v2[d2] = a;
    } else if (wid == 2*Dd){
        float a = 0.f;
        for (int j = lane; j < Dd; j += 32) a += bq[j] * bk[j];
        a = warp_sum(a);
        if (!lane) g_c0 = a;
    }
}

// ---------------- band dot products: one warp per (b,s) row ----------------
__global__ __launch_bounds__(256) void band_dots_kernel(){
    int wid  = (blockIdx.x*256 + threadIdx.x) >> 5;
    int lane = threadIdx.x & 31;
    if (wid >= BS) return;
    int s = wid & (Ss-1);
    const float* h  = g_h + (size_t)wid * Dd;
    const float* yu = g_Y + (size_t)(wid+1) * Dd;
    const float* yd = g_Y + (size_t)(wid-1) * Dd;
    bool hasU = (s < Ss-1), hasD = (s > 0);
    float au=0.f, ad=0.f, a1=0.f, a2=0.f;
#pragma unroll
    for (int j = lane*4; j < Dd; j += 128){
        float4 hv = *(const float4*)(h + j);
        float4 w1 = *(const float4*)(g_v1 + j);
        float4 w2 = *(const float4*)(g_v2 + j);
        a1 += hv.x*w1.x + hv.y*w1.y + hv.z*w1.z + hv.w*w1.w;
        a2 += hv.x*w2.x + hv.y*w2.y + hv.z*w2.z + hv.w*w2.w;
        if (hasU){ float4 y = *(const float4*)(yu + j);
                   au += hv.x*y.x + hv.y*y.y + hv.z*y.z + hv.w*y.w; }
        if (hasD){ float4 y = *(const float4*)(yd + j);
                   ad += hv.x*y.x + hv.y*y.y + hv.z*y.z + hv.w*y.w; }
    }
    au = warp_sum(au); ad = warp_sum(ad); a1 = warp_sum(a1); a2 = warp_sum(a2);
    if (lane == 0){ g_du[wid]=au; g_dd[wid]=ad; g_a1v[wid]=a1; g_a2v[wid]=a2; }
}

// ---- softmax weights for one row: returns (up_weight, down_weight) ----
__device__ __forceinline__ float2 softpair(const int* __restrict__ am, int b, int s){
    int row = b*Ss + s;
    const int* amr = am + (size_t)b*SSQ + (size_t)s*Ss;
    bool au = (s < Ss-1) && (amr[s+1] != 0);
    bool ad = (s > 0)    && (amr[s-1] != 0);
    float su = 0.f, sd = 0.f;
    if (au || ad){
        float c0 = g_c0;
        const float NEG = -3.0e38f;
        float eu = au ? (g_du[row] + g_a1v[row] + g_a2v[row+1] + c0) * (1.f/Dd) : NEG;
        float ed = ad ? (g_dd[row] + g_a1v[row] + g_a2v[row-1] + c0) * (1.f/Dd) : NEG;
        float m  = fmaxf(eu, ed);
        float xu = au ? __expf(eu - m) : 0.f;
        float xd = ad ? __expf(ed - m) : 0.f;
        float inv = 1.f / (xu + xd);
        su = xu * inv; sd = xd * inv;
    }
    return make_float2(su, sd);
}

// ---------------- fused band: softmax + n values + L = log(nsup+1e-9) ----------------
__global__ __launch_bounds__(256) void band_n_kernel(const int* __restrict__ am,
                                                     const float* __restrict__ prior){
    int row = blockIdx.x*256 + threadIdx.x;
    if (row >= BS) return;
    int b = row >> 11, s = row & (Ss-1);
    if (s == Ss-1){ g_Lg[row] = 0.f; return; }
    float su = softpair(am, b, s).x;      // softn[s, s+1]
    float sd = softpair(am, b, s+1).y;    // softn[s+1, s]
    float nv = sqrtf(su * sd + 1e-9f);
    size_t base = (size_t)b*SSQ + (size_t)s*Ss;
    float p1 = prior[base + s + 1];
    float p2 = prior[base + Ss + s];
    float nsup = p1 + (1.f - p1) * nv;
    float nsub = p2 + (1.f - p2) * nv;
    g_nsup[row] = nsup; g_nsub[row] = nsub;
    g_Lg[row] = logf(nsup + 1e-9f);
}

// ---------------- exclusive prefix sum of L per batch ----------------
__global__ __launch_bounds__(1024) void scan_kernel(){
    __shared__ float bufA[Ss], bufB[Ss];
    int b = blockIdx.x;
    float* in = bufA; float* out = bufB;
    for (int i = threadIdx.x; i < Ss; i += 1024) in[i] = g_Lg[b*Ss + i];
    __syncthreads();
    for (int off = 1; off < Ss; off <<= 1){
        for (int i = threadIdx.x; i < Ss; i += 1024)
            out[i] = (i >= off) ? (in[i] + in[i-off]) : in[i];
        __syncthreads();
        float* t = in; in = out; out = t;
    }
    for (int i = threadIdx.x; i < Ss; i += 1024)
        g_P[b*Ss + i] = (i == 0) ? 0.f : in[i-1];
}

// ---------------- dense pass: full g and n, with band patch fused ----------------
__global__ __launch_bounds__(256) void dense_kernel(const float* __restrict__ prior,
                                                    float* __restrict__ gO,
                                                    float* __restrict__ nO){
    __shared__ float sP[Ss];
    int b  = blockIdx.x >> 8;          // 256 blocks per batch
    int r0 = (blockIdx.x & 255) * 8;   // 8 rows per block
    const float* Pb = g_P + b*Ss;
    for (int i = threadIdx.x; i < Ss; i += 256) sP[i] = Pb[i];
    __syncthreads();
    const float CC  = 3.16227766016838e-5f;  // sqrt(1e-9)
    const float OMC = 1.f - CC;
    size_t bbase = (size_t)b * SSQ;
#pragma unroll
    for (int r = 0; r < 8; r++){
        int i = r0 + r;
        float Pi = sP[i];
        size_t rbase = bbase + (size_t)i*Ss;
#pragma unroll
        for (int ccI = 0; ccI < 2; ccI++){
            int c  = threadIdx.x + ccI*256;
            int k0 = c * 4;
            float4 pr = *(const float4*)(prior + rbase + k0);
            float4 pk = *(const float4*)(sP + k0);
            float4 nv;
            nv.x = fmaf(pr.x, OMC, CC);
            nv.y = fmaf(pr.y, OMC, CC);
            nv.z = fmaf(pr.z, OMC, CC);
            nv.w = fmaf(pr.w, OMC, CC);
            float dx = (k0+0 > i) ? pk.x - Pi : Pi - pk.x;
            float dy = (k0+1 > i) ? pk.y - Pi : Pi - pk.y;
            float dz = (k0+2 > i) ? pk.z - Pi : Pi - pk.z;
            float dw = (k0+3 > i) ? pk.w - Pi : Pi - pk.w;
            float dm = fmaxf(fmaxf(dx,dy), fmaxf(dz,dw));
            float4 gv;
            if (__ballot_sync(0xffffffffu, dm > -30.f)){   // warp-uniform exp skip
                gv.x = __expf(dx) + 1e-9f;
                gv.y = __expf(dy) + 1e-9f;
                gv.z = __expf(dz) + 1e-9f;
                gv.w = __expf(dw) + 1e-9f;
            } else {
                gv.x = gv.y = gv.z = gv.w = 1e-9f;
            }
            *(float4*)(nO + rbase + k0) = nv;
            *(float4*)(gO + rbase + k0) = gv;
        }
    }
    __syncthreads();
    // fused patch: band n entries + g diagonal for this block's 8 rows
    if (threadIdx.x < 8){
        int i = r0 + threadIdx.x;
        int rowg = b*Ss + i;
        const float CC2 = 3.16227766016838e-5f;
        float pd = prior[bbase + (size_t)i*Ss + i];
        gO[bbase + (size_t)i*Ss + i] = fmaf(pd, 1.f - CC2, CC2);   // g[i,i] = n[i,i]
        if (i < Ss-1) nO[bbase + (size_t)i*Ss + i + 1] = g_nsup[rowg];
        if (i > 0)    nO[bbase + (size_t)i*Ss + i - 1] = g_nsub[rowg-1];
    }
}

// ---------------- launch ----------------
extern "C" void kernel_launch(void* const* d_in, const int* in_sizes, int n_in,
                              void* d_out, int out_size){
    const float* hidden = (const float*)d_in[0];
    const int*   amask  = (const int*)  d_in[1];
    const float* prior  = (const float*)d_in[2];
    const float* lnw    = (const float*)d_in[3];
    const float* lnb    = (const float*)d_in[4];
    const float* wq     = (const float*)d_in[5];
    const float* bq     = (const float*)d_in[6];
    const float* wk     = (const float*)d_in[7];
    const float* bk     = (const float*)d_in[8];
    float* gO = (float*)d_out;
    float* nO = gO + (size_t)Bb * SSQ;

    ln_kernel<<<BS, 256>>>(hidden, lnw, lnb);
    gemm_M_kernel<<<dim3(Dd/128, Dd/128), 256>>>(wq, wk);
    biasvec_kernel<<<193, 256>>>(wq, wk, bq, bk);
    gemm_Y_kernel<<<dim3(Dd/128, BS/128), 256>>>();
    band_dots_kernel<<<BS/8, 256>>>();
    band_n_kernel<<<BS/256, 256>>>(amask, prior);
    scan_kernel<<<Bb, 1024>>>();
    dense_kernel<<<Bb*(Ss/8), 256>>>(prior, gO, nO);
}

// round 3
// speedup vs baseline: 2.3399x; 1.0922x over previous
#include <cuda_runtime.h>
#include <math.h>
#include <stdint.h>

#define Bb 4
#define Ss 2048
#define Dd 768
#define BS (Bb*Ss)
#define SSQ ((size_t)Ss*(size_t)Ss)
#define KSPLIT 4
#define KCHUNK (Dd/KSPLIT)

// -------- scratch (static device globals; no runtime allocation) --------
static __device__ float g_h[(size_t)BS*Dd];         // layernorm output (tf32-rounded bits)
static __device__ float g_Y[(size_t)BS*Dd];         // Y = H * M^T
static __device__ float g_M[Dd*Dd];                 // M = Wq * Wk^T (tf32-rounded bits)
static __device__ float g_Mp[KSPLIT*Dd*Dd];         // split-K partials
static __device__ float g_v1[Dd];
static __device__ float g_v2[Dd];
static __device__ float g_c0;
static __device__ float g_du[BS], g_dd[BS], g_a1v[BS], g_a2v[BS];
static __device__ float g_nsup[BS], g_nsub[BS], g_Lg[BS];
static __device__ float g_P[BS];

__device__ __forceinline__ float warp_sum(float v){
#pragma unroll
    for (int o = 16; o; o >>= 1) v += __shfl_xor_sync(0xffffffffu, v, o);
    return v;
}
__device__ __forceinline__ uint32_t f2tf32(float x){
    uint32_t r; asm("cvt.rna.tf32.f32 %0, %1;" : "=r"(r) : "f"(x)); return r;
}

// ---------------- LayerNorm: one block (256 thr) per row; writes tf32-rounded h ----------------
__global__ __launch_bounds__(256) void ln_kernel(const float* __restrict__ x,
                                                 const float* __restrict__ w,
                                                 const float* __restrict__ b){
    int row = blockIdx.x;
    const float* xr = x + (size_t)row * Dd;
    int t = threadIdx.x;
    float v0 = xr[t], v1 = xr[t+256], v2 = xr[t+512];
    float s = v0 + v1 + v2;
    float q = v0*v0 + v1*v1 + v2*v2;
    __shared__ float rs[8], rq[8];
    s = warp_sum(s); q = warp_sum(q);
    if ((t & 31) == 0){ rs[t>>5] = s; rq[t>>5] = q; }
    __syncthreads();
    if (t < 32){
        float a = (t < 8) ? rs[t] : 0.f;
        float c = (t < 8) ? rq[t] : 0.f;
#pragma unroll
        for (int o = 4; o; o >>= 1){
            a += __shfl_xor_sync(0xffffffffu, a, o);
            c += __shfl_xor_sync(0xffffffffu, c, o);
        }
        if (t == 0){ rs[0] = a; rq[0] = c; }
    }
    __syncthreads();
    float mu   = rs[0] * (1.f/Dd);
    float var  = fmaxf(rq[0] * (1.f/Dd) - mu*mu, 0.f);
    float rstd = rsqrtf(var + 1e-12f);
    float* hr = g_h + (size_t)row * Dd;
    hr[t]     = __uint_as_float(f2tf32((v0 - mu) * rstd * w[t]     + b[t]));
    hr[t+256] = __uint_as_float(f2tf32((v1 - mu) * rstd * w[t+256] + b[t+256]));
    hr[t+512] = __uint_as_float(f2tf32((v2 - mu) * rstd * w[t+512] + b[t+512]));
}

// ================= tf32 tensor-core NT GEMM (3-stage, raw-bit operands) =================
__device__ __forceinline__ void cp16(uint32_t dst, const void* src){
    asm volatile("cp.async.ca.shared.global [%0], [%1], 16;" :: "r"(dst), "l"(src));
}

#define SE (128*20)   // floats per stage per operand

__device__ __forceinline__ void gemm_nt_tf32_body(const float* __restrict__ A,
                                                  const float* __restrict__ B,
                                                  float* __restrict__ C,
                                                  int lda, int ldc, int kLen){
    extern __shared__ float smem[];
    float* Asm = smem;            // 3 * SE
    float* Bsm = smem + 3*SE;     // 3 * SE
    const int tid = threadIdx.x;
    const int bm = blockIdx.y * 128, bn = blockIdx.x * 128;
    const int wid = tid >> 5, lane = tid & 31;
    const int wm = (wid >> 2) * 64, wn = (wid & 3) * 32;   // 2x4 warp grid, 64x32 warp tile
    const int g = lane >> 2, qc = lane & 3;
    const int lrow = tid >> 2, lkq = tid & 3;

    const float* Ap0 = A + (size_t)(bm + lrow)      * lda + lkq*4;
    const float* Ap1 = A + (size_t)(bm + lrow + 64) * lda + lkq*4;
    const float* Bp0 = B + (size_t)(bn + lrow)      * lda + lkq*4;
    const float* Bp1 = B + (size_t)(bn + lrow + 64) * lda + lkq*4;
    uint32_t sa0[3], sa1[3], sb0[3], sb1[3];
#pragma unroll
    for (int s = 0; s < 3; s++){
        sa0[s] = (uint32_t)__cvta_generic_to_shared(Asm + s*SE + lrow*20      + lkq*4);
        sa1[s] = (uint32_t)__cvta_generic_to_shared(Asm + s*SE + (lrow+64)*20 + lkq*4);
        sb0[s] = (uint32_t)__cvta_generic_to_shared(Bsm + s*SE + lrow*20      + lkq*4);
        sb1[s] = (uint32_t)__cvta_generic_to_shared(Bsm + s*SE + (lrow+64)*20 + lkq*4);
    }

    float acc[4][4][4];
#pragma unroll
    for (int i = 0; i < 4; i++)
#pragma unroll
        for (int j = 0; j < 4; j++)
#pragma unroll
            for (int k = 0; k < 4; k++) acc[i][j][k] = 0.f;

    const int niter = kLen / 16;
    // prologue: stages 0 and 1
#pragma unroll
    for (int p = 0; p < 2; p++){
        const int k0 = p * 16;
        cp16(sa0[p], Ap0 + k0); cp16(sa1[p], Ap1 + k0);
        cp16(sb0[p], Bp0 + k0); cp16(sb1[p], Bp1 + k0);
        asm volatile("cp.async.commit_group;");
    }

    for (int it = 0; it < niter; it++){
        const int st = it % 3;
        if (it + 1 < niter) asm volatile("cp.async.wait_group 1;");
        else                asm volatile("cp.async.wait_group 0;");
        __syncthreads();
        if (it + 2 < niter){
            const int ns = (it + 2) % 3;
            const int k0 = (it + 2) * 16;
            cp16(sa0[ns], Ap0 + k0); cp16(sa1[ns], Ap1 + k0);
            cp16(sb0[ns], Bp0 + k0); cp16(sb1[ns], Bp1 + k0);
            asm volatile("cp.async.commit_group;");
        }
        const float* as = Asm + st*SE;
        const float* bs = Bsm + st*SE;
#pragma unroll
        for (int ks = 0; ks < 2; ks++){
            const int kk = ks * 8;
            uint32_t af[4][4], bf[4][2];
#pragma unroll
            for (int tm = 0; tm < 4; tm++){
                int r0 = wm + tm*16 + g;
                af[tm][0] = __float_as_uint(as[r0*20     + kk+qc  ]);
                af[tm][1] = __float_as_uint(as[(r0+8)*20 + kk+qc  ]);
                af[tm][2] = __float_as_uint(as[r0*20     + kk+qc+4]);
                af[tm][3] = __float_as_uint(as[(r0+8)*20 + kk+qc+4]);
            }
#pragma unroll
            for (int tn = 0; tn < 4; tn++){
                int n0 = wn + tn*8 + g;
                bf[tn][0] = __float_as_uint(bs[n0*20 + kk+qc  ]);
                bf[tn][1] = __float_as_uint(bs[n0*20 + kk+qc+4]);
            }
#pragma unroll
            for (int tm = 0; tm < 4; tm++)
#pragma unroll
                for (int tn = 0; tn < 4; tn++)
                    asm volatile(
                        "mma.sync.aligned.m16n8k8.row.col.f32.tf32.tf32.f32 "
                        "{%0,%1,%2,%3},{%4,%5,%6,%7},{%8,%9},{%0,%1,%2,%3};"
                        : "+f"(acc[tm][tn][0]), "+f"(acc[tm][tn][1]),
                          "+f"(acc[tm][tn][2]), "+f"(acc[tm][tn][3])
                        : "r"(af[tm][0]), "r"(af[tm][1]), "r"(af[tm][2]), "r"(af[tm][3]),
                          "r"(bf[tn][0]), "r"(bf[tn][1]));
        }
        __syncthreads();
    }

#pragma unroll
    for (int tm = 0; tm < 4; tm++){
        int r = bm + wm + tm*16 + g;
#pragma unroll
        for (int tn = 0; tn < 4; tn++){
            int cc = bn + wn + tn*8 + qc*2;
            *(float2*)&C[(size_t)r*ldc + cc]     = make_float2(acc[tm][tn][0], acc[tm][tn][1]);
            *(float2*)&C[(size_t)(r+8)*ldc + cc] = make_float2(acc[tm][tn][2], acc[tm][tn][3]);
        }
    }
}

// split-K partial GEMM for M: grid (6,6,KSPLIT)
__global__ __launch_bounds__(256) void gemm_M_kernel(const float* __restrict__ wq,
                                                     const float* __restrict__ wk){
    int z = blockIdx.z;
    gemm_nt_tf32_body(wq + z*KCHUNK, wk + z*KCHUNK, g_Mp + (size_t)z*Dd*Dd,
                      Dd, Dd, KCHUNK);
}
// reduce partials + tf32 round
__global__ __launch_bounds__(256) void reduceM_kernel(){
    int i = blockIdx.x*256 + threadIdx.x;          // float4 index
    const int N4 = Dd*Dd/4;
    if (i >= N4) return;
    const float4* p = (const float4*)g_Mp;
    float4 a = p[i], b = p[i+N4], c = p[i+2*N4], d = p[i+3*N4];
    float4 o;
    o.x = __uint_as_float(f2tf32(a.x + b.x + c.x + d.x));
    o.y = __uint_as_float(f2tf32(a.y + b.y + c.y + d.y));
    o.z = __uint_as_float(f2tf32(a.z + b.z + c.z + d.z));
    o.w = __uint_as_float(f2tf32(a.w + b.w + c.w + d.w));
    ((float4*)g_M)[i] = o;
}

__global__ __launch_bounds__(256) void gemm_Y_kernel(){
    gemm_nt_tf32_body(g_h, g_M, g_Y, Dd, Dd, Dd);  // Y[t,d] = sum_e h[t,e]*M[d,e]
}

// ---------------- bias vectors: v1 = Wq*bk, v2 = Wk*bq, c0 = bq.bk ----------------
__global__ __launch_bounds__(256) void biasvec_kernel(const float* __restrict__ wq,
                                                      const float* __restrict__ wk,
                                                      const float* __restrict__ bq,
                                                      const float* __restrict__ bk){
    int wid  = (blockIdx.x*256 + threadIdx.x) >> 5;
    int lane = threadIdx.x & 31;
    if (wid < Dd){
        const float* r = wq + (size_t)wid * Dd;
        float a = 0.f;
        for (int j = lane; j < Dd; j += 32) a += r[j] * bk[j];
        a = warp_sum(a);
        if (!lane) g_v1[wid] = a;
    } else if (wid < 2*Dd){
        int d2 = wid - Dd;
        const float* r = wk + (size_t)d2 * Dd;
        float a = 0.f;
        for (int j = lane; j < Dd; j += 32) a += r[j] * bq[j];
        a = warp_sum(a);
        if (!lane) g_v2[d2] = a;
    } else if (wid == 2*Dd){
        float a = 0.f;
        for (int j = lane; j < Dd; j += 32) a += bq[j] * bk[j];
        a = warp_sum(a);
        if (!lane) g_c0 = a;
    }
}

// ---------------- band dot products: one warp per (b,s) row ----------------
__global__ __launch_bounds__(256) void band_dots_kernel(){
    int wid  = (blockIdx.x*256 + threadIdx.x) >> 5;
    int lane = threadIdx.x & 31;
    if (wid >= BS) return;
    int s = wid & (Ss-1);
    const float* h  = g_h + (size_t)wid * Dd;
    const float* yu = g_Y + (size_t)(wid+1) * Dd;
    const float* yd = g_Y + (size_t)(wid-1) * Dd;
    bool hasU = (s < Ss-1), hasD = (s > 0);
    float au=0.f, ad=0.f, a1=0.f, a2=0.f;
#pragma unroll
    for (int j = lane*4; j < Dd; j += 128){
        float4 hv = *(const float4*)(h + j);
        float4 w1 = *(const float4*)(g_v1 + j);
        float4 w2 = *(const float4*)(g_v2 + j);
        a1 += hv.x*w1.x + hv.y*w1.y + hv.z*w1.z + hv.w*w1.w;
        a2 += hv.x*w2.x + hv.y*w2.y + hv.z*w2.z + hv.w*w2.w;
        if (hasU){ float4 y = *(const float4*)(yu + j);
                   au += hv.x*y.x + hv.y*y.y + hv.z*y.z + hv.w*y.w; }
        if (hasD){ float4 y = *(const float4*)(yd + j);
                   ad += hv.x*y.x + hv.y*y.y + hv.z*y.z + hv.w*y.w; }
    }
    au = warp_sum(au); ad = warp_sum(ad); a1 = warp_sum(a1); a2 = warp_sum(a2);
    if (lane == 0){ g_du[wid]=au; g_dd[wid]=ad; g_a1v[wid]=a1; g_a2v[wid]=a2; }
}

// ---- softmax weights for one row: returns (up_weight, down_weight) ----
__device__ __forceinline__ float2 softpair(const int* __restrict__ am, int b, int s){
    int row = b*Ss + s;
    const int* amr = am + (size_t)b*SSQ + (size_t)s*Ss;
    bool au = (s < Ss-1) && (amr[s+1] != 0);
    bool ad = (s > 0)    && (amr[s-1] != 0);
    float su = 0.f, sd = 0.f;
    if (au || ad){
        float c0 = g_c0;
        const float NEG = -3.0e38f;
        float eu = au ? (g_du[row] + g_a1v[row] + g_a2v[row+1] + c0) * (1.f/Dd) : NEG;
        float ed = ad ? (g_dd[row] + g_a1v[row] + g_a2v[row-1] + c0) * (1.f/Dd) : NEG;
        float m  = fmaxf(eu, ed);
        float xu = au ? __expf(eu - m) : 0.f;
        float xd = ad ? __expf(ed - m) : 0.f;
        float inv = 1.f / (xu + xd);
        su = xu * inv; sd = xd * inv;
    }
    return make_float2(su, sd);
}

// ---------------- fused band: softmax + n values + L = log(nsup+1e-9) ----------------
__global__ __launch_bounds__(256) void band_n_kernel(const int* __restrict__ am,
                                                     const float* __restrict__ prior){
    int row = blockIdx.x*256 + threadIdx.x;
    if (row >= BS) return;
    int b = row >> 11, s = row & (Ss-1);
    if (s == Ss-1){ g_Lg[row] = 0.f; return; }
    float su = softpair(am, b, s).x;      // softn[s, s+1]
    float sd = softpair(am, b, s+1).y;    // softn[s+1, s]
    float nv = sqrtf(su * sd + 1e-9f);
    size_t base = (size_t)b*SSQ + (size_t)s*Ss;
    float p1 = prior[base + s + 1];
    float p2 = prior[base + Ss + s];
    float nsup = p1 + (1.f - p1) * nv;
    float nsub = p2 + (1.f - p2) * nv;
    g_nsup[row] = nsup; g_nsub[row] = nsub;
    g_Lg[row] = logf(nsup + 1e-9f);
}

// ---------------- exclusive prefix sum of L per batch ----------------
__global__ __launch_bounds__(1024) void scan_kernel(){
    __shared__ float bufA[Ss], bufB[Ss];
    int b = blockIdx.x;
    float* in = bufA; float* out = bufB;
    for (int i = threadIdx.x; i < Ss; i += 1024) in[i] = g_Lg[b*Ss + i];
    __syncthreads();
    for (int off = 1; off < Ss; off <<= 1){
        for (int i = threadIdx.x; i < Ss; i += 1024)
            out[i] = (i >= off) ? (in[i] + in[i-off]) : in[i];
        __syncthreads();
        float* t = in; in = out; out = t;
    }
    for (int i = threadIdx.x; i < Ss; i += 1024)
        g_P[b*Ss + i] = (i == 0) ? 0.f : in[i-1];
}

// ---------------- dense pass: full g and n, with band patch fused ----------------
__global__ __launch_bounds__(256) void dense_kernel(const float* __restrict__ prior,
                                                    float* __restrict__ gO,
                                                    float* __restrict__ nO){
    __shared__ float sP[Ss];
    int b  = blockIdx.x >> 8;          // 256 blocks per batch
    int r0 = (blockIdx.x & 255) * 8;   // 8 rows per block
    const float* Pb = g_P + b*Ss;
    for (int i = threadIdx.x; i < Ss; i += 256) sP[i] = Pb[i];
    __syncthreads();
    const float CC  = 3.16227766016838e-5f;  // sqrt(1e-9)
    const float OMC = 1.f - CC;
    size_t bbase = (size_t)b * SSQ;
#pragma unroll
    for (int r = 0; r < 8; r++){
        int i = r0 + r;
        float Pi = sP[i];
        size_t rbase = bbase + (size_t)i*Ss;
#pragma unroll
        for (int ccI = 0; ccI < 2; ccI++){
            int c  = threadIdx.x + ccI*256;
            int k0 = c * 4;
            float4 pr = *(const float4*)(prior + rbase + k0);
            float4 pk = *(const float4*)(sP + k0);
            float4 nv;
            nv.x = fmaf(pr.x, OMC, CC);
            nv.y = fmaf(pr.y, OMC, CC);
            nv.z = fmaf(pr.z, OMC, CC);
            nv.w = fmaf(pr.w, OMC, CC);
            float dx = (k0+0 > i) ? pk.x - Pi : Pi - pk.x;
            float dy = (k0+1 > i) ? pk.y - Pi : Pi - pk.y;
            float dz = (k0+2 > i) ? pk.z - Pi : Pi - pk.z;
            float dw = (k0+3 > i) ? pk.w - Pi : Pi - pk.w;
            float dm = fmaxf(fmaxf(dx,dy), fmaxf(dz,dw));
            float4 gv;
            if (__ballot_sync(0xffffffffu, dm > -30.f)){   // warp-uniform exp skip
                gv.x = __expf(dx) + 1e-9f;
                gv.y = __expf(dy) + 1e-9f;
                gv.z = __expf(dz) + 1e-9f;
                gv.w = __expf(dw) + 1e-9f;
            } else {
                gv.x = gv.y = gv.z = gv.w = 1e-9f;
            }
            *(float4*)(nO + rbase + k0) = nv;
            *(float4*)(gO + rbase + k0) = gv;
        }
    }
    __syncthreads();
    // fused patch: band n entries + g diagonal for this block's 8 rows
    if (threadIdx.x < 8){
        int i = r0 + threadIdx.x;
        int rowg = b*Ss + i;
        const float CC2 = 3.16227766016838e-5f;
        float pd = prior[bbase + (size_t)i*Ss + i];
        gO[bbase + (size_t)i*Ss + i] = fmaf(pd, 1.f - CC2, CC2);   // g[i,i] = n[i,i]
        if (i < Ss-1) nO[bbase + (size_t)i*Ss + i + 1] = g_nsup[rowg];
        if (i > 0)    nO[bbase + (size_t)i*Ss + i - 1] = g_nsub[rowg-1];
    }
}

// ---------------- launch ----------------
extern "C" void kernel_launch(void* const* d_in, const int* in_sizes, int n_in,
                              void* d_out, int out_size){
    const float* hidden = (const float*)d_in[0];
    const int*   amask  = (const int*)  d_in[1];
    const float* prior  = (const float*)d_in[2];
    const float* lnw    = (const float*)d_in[3];
    const float* lnb    = (const float*)d_in[4];
    const float* wq     = (const float*)d_in[5];
    const float* bq     = (const float*)d_in[6];
    const float* wk     = (const float*)d_in[7];
    const float* bk     = (const float*)d_in[8];
    float* gO = (float*)d_out;
    float* nO = gO + (size_t)Bb * SSQ;

    const int GEMM_SMEM = 6*SE*sizeof(float);   // 61440 B
    cudaFuncSetAttribute(gemm_M_kernel, cudaFuncAttributeMaxDynamicSharedMemorySize, GEMM_SMEM);
    cudaFuncSetAttribute(gemm_Y_kernel, cudaFuncAttributeMaxDynamicSharedMemorySize, GEMM_SMEM);

    ln_kernel<<<BS, 256>>>(hidden, lnw, lnb);
    gemm_M_kernel<<<dim3(Dd/128, Dd/128, KSPLIT), 256, GEMM_SMEM>>>(wq, wk);
    reduceM_kernel<<<(Dd*Dd/4 + 255)/256, 256>>>();
    biasvec_kernel<<<193, 256>>>(wq, wk, bq, bk);
    gemm_Y_kernel<<<dim3(Dd/128, BS/128), 256, GEMM_SMEM>>>();
    band_dots_kernel<<<BS/8, 256>>>();
    band_n_kernel<<<BS/256, 256>>>(amask, prior);
    scan_kernel<<<Bb, 1024>>>();
    dense_kernel<<<Bb*(Ss/8), 256>>>(prior, gO, nO);
}

// round 9
// speedup vs baseline: 2.4750x; 1.0577x over previous
#include <cuda_runtime.h>
#include <math.h>
#include <stdint.h>

#define Bb 4
#define Ss 2048
#define Dd 768
#define BS (Bb*Ss)
#define SSQ ((size_t)Ss*(size_t)Ss)
#define KSPLIT 4
#define KCHUNK (Dd/KSPLIT)

// -------- scratch (static device globals; no runtime allocation) --------
static __device__ float g_h[(size_t)BS*Dd];         // layernorm output (tf32-rounded bits)
static __device__ float g_Y[(size_t)BS*Dd];         // Y = H * M^T
static __device__ float g_M[Dd*Dd];                 // M = Wq * Wk^T (tf32-rounded bits)
static __device__ float g_Mp[KSPLIT*Dd*Dd];         // split-K partials
static __device__ float g_v1[Dd];
static __device__ float g_v2[Dd];
static __device__ float g_c0;
static __device__ float g_du[BS], g_dd[BS], g_a1v[BS], g_a2v[BS];
static __device__ float g_nsup[BS], g_nsub[BS];
static __device__ float g_P[BS];

__device__ __forceinline__ float warp_sum(float v){
#pragma unroll
    for (int o = 16; o; o >>= 1) v += __shfl_xor_sync(0xffffffffu, v, o);
    return v;
}
__device__ __forceinline__ uint32_t f2tf32(float x){
    uint32_t r; asm("cvt.rna.tf32.f32 %0, %1;" : "=r"(r) : "f"(x)); return r;
}

// ---------------- LayerNorm: one block (256 thr) per row; writes tf32-rounded h ----------------
__global__ __launch_bounds__(256) void ln_kernel(const float* __restrict__ x,
                                                 const float* __restrict__ w,
                                                 const float* __restrict__ b){
    int row = blockIdx.x;
    const float* xr = x + (size_t)row * Dd;
    int t = threadIdx.x;
    float v0 = xr[t], v1 = xr[t+256], v2 = xr[t+512];
    float s = v0 + v1 + v2;
    float q = v0*v0 + v1*v1 + v2*v2;
    __shared__ float rs[8], rq[8];
    s = warp_sum(s); q = warp_sum(q);
    if ((t & 31) == 0){ rs[t>>5] = s; rq[t>>5] = q; }
    __syncthreads();
    if (t < 32){
        float a = (t < 8) ? rs[t] : 0.f;
        float c = (t < 8) ? rq[t] : 0.f;
#pragma unroll
        for (int o = 4; o; o >>= 1){
            a += __shfl_xor_sync(0xffffffffu, a, o);
            c += __shfl_xor_sync(0xffffffffu, c, o);
        }
        if (t == 0){ rs[0] = a; rq[0] = c; }
    }
    __syncthreads();
    float mu   = rs[0] * (1.f/Dd);
    float var  = fmaxf(rq[0] * (1.f/Dd) - mu*mu, 0.f);
    float rstd = rsqrtf(var + 1e-12f);
    float* hr = g_h + (size_t)row * Dd;
    hr[t]     = __uint_as_float(f2tf32((v0 - mu) * rstd * w[t]     + b[t]));
    hr[t+256] = __uint_as_float(f2tf32((v1 - mu) * rstd * w[t+256] + b[t+256]));
    hr[t+512] = __uint_as_float(f2tf32((v2 - mu) * rstd * w[t+512] + b[t+512]));
}

// ================= tf32 tensor-core NT GEMM (4-stage, raw-bit operands) =================
__device__ __forceinline__ void cp16(uint32_t dst, const void* src){
    asm volatile("cp.async.cg.shared.global [%0], [%1], 16;" :: "r"(dst), "l"(src));
}

#define SE (128*20)      // floats per stage per operand
#define NSTAGE 4

__device__ __forceinline__ void gemm_nt_tf32_body(const float* __restrict__ A,
                                                  const float* __restrict__ B,
                                                  float* __restrict__ C,
                                                  int lda, int ldc, int kLen){
    extern __shared__ float smem[];
    float* Asm = smem;                 // NSTAGE * SE
    float* Bsm = smem + NSTAGE*SE;     // NSTAGE * SE
    const int tid = threadIdx.x;
    const int bm = blockIdx.y * 128, bn = blockIdx.x * 128;
    const int wid = tid >> 5, lane = tid & 31;
    const int wm = (wid >> 2) * 64, wn = (wid & 3) * 32;   // 2x4 warp grid, 64x32 warp tile
    const int g = lane >> 2, qc = lane & 3;
    const int lrow = tid >> 2, lkq = tid & 3;

    const float* Ap0 = A + (size_t)(bm + lrow)      * lda + lkq*4;
    const float* Ap1 = A + (size_t)(bm + lrow + 64) * lda + lkq*4;
    const float* Bp0 = B + (size_t)(bn + lrow)      * lda + lkq*4;
    const float* Bp1 = B + (size_t)(bn + lrow + 64) * lda + lkq*4;
    uint32_t sa0[NSTAGE], sa1[NSTAGE], sb0[NSTAGE], sb1[NSTAGE];
#pragma unroll
    for (int s = 0; s < NSTAGE; s++){
        sa0[s] = (uint32_t)__cvta_generic_to_shared(Asm + s*SE + lrow*20      + lkq*4);
        sa1[s] = (uint32_t)__cvta_generic_to_shared(Asm + s*SE + (lrow+64)*20 + lkq*4);
        sb0[s] = (uint32_t)__cvta_generic_to_shared(Bsm + s*SE + lrow*20      + lkq*4);
        sb1[s] = (uint32_t)__cvta_generic_to_shared(Bsm + s*SE + (lrow+64)*20 + lkq*4);
    }

    float acc[4][4][4];
#pragma unroll
    for (int i = 0; i < 4; i++)
#pragma unroll
        for (int j = 0; j < 4; j++)
#pragma unroll
            for (int k = 0; k < 4; k++) acc[i][j][k] = 0.f;

    const int niter = kLen / 16;
    // prologue: stages 0..2
#pragma unroll
    for (int p = 0; p < NSTAGE-1; p++){
        const int k0 = p * 16;
        cp16(sa0[p], Ap0 + k0); cp16(sa1[p], Ap1 + k0);
        cp16(sb0[p], Bp0 + k0); cp16(sb1[p], Bp1 + k0);
        asm volatile("cp.async.commit_group;");
    }

    for (int it = 0; it < niter; it++){
        const int st = it & (NSTAGE-1);
        if      (it <  niter-2) asm volatile("cp.async.wait_group 2;");
        else if (it == niter-2) asm volatile("cp.async.wait_group 1;");
        else                    asm volatile("cp.async.wait_group 0;");
        __syncthreads();
        if (it + NSTAGE-1 < niter){
            const int ns = (it + NSTAGE-1) & (NSTAGE-1);
            const int k0 = (it + NSTAGE-1) * 16;
            cp16(sa0[ns], Ap0 + k0); cp16(sa1[ns], Ap1 + k0);
            cp16(sb0[ns], Bp0 + k0); cp16(sb1[ns], Bp1 + k0);
            asm volatile("cp.async.commit_group;");
        }
        const float* as = Asm + st*SE;
        const float* bs = Bsm + st*SE;
#pragma unroll
        for (int ks = 0; ks < 2; ks++){
            const int kk = ks * 8;
            uint32_t af[4][4], bf[4][2];
#pragma unroll
            for (int tm = 0; tm < 4; tm++){
                int r0 = wm + tm*16 + g;
                af[tm][0] = __float_as_uint(as[r0*20     + kk+qc  ]);
                af[tm][1] = __float_as_uint(as[(r0+8)*20 + kk+qc  ]);
                af[tm][2] = __float_as_uint(as[r0*20     + kk+qc+4]);
                af[tm][3] = __float_as_uint(as[(r0+8)*20 + kk+qc+4]);
            }
#pragma unroll
            for (int tn = 0; tn < 4; tn++){
                int n0 = wn + tn*8 + g;
                bf[tn][0] = __float_as_uint(bs[n0*20 + kk+qc  ]);
                bf[tn][1] = __float_as_uint(bs[n0*20 + kk+qc+4]);
            }
#pragma unroll
            for (int tm = 0; tm < 4; tm++)
#pragma unroll
                for (int tn = 0; tn < 4; tn++)
                    asm volatile(
                        "mma.sync.aligned.m16n8k8.row.col.f32.tf32.tf32.f32 "
                        "{%0,%1,%2,%3},{%4,%5,%6,%7},{%8,%9},{%0,%1,%2,%3};"
                        : "+f"(acc[tm][tn][0]), "+f"(acc[tm][tn][1]),
                          "+f"(acc[tm][tn][2]), "+f"(acc[tm][tn][3])
                        : "r"(af[tm][0]), "r"(af[tm][1]), "r"(af[tm][2]), "r"(af[tm][3]),
                          "r"(bf[tn][0]), "r"(bf[tn][1]));
        }
        // NOTE: no bottom barrier — with >=3 stages the write stage (it+3)%4 is
        // the stage read at iteration it-1, and the top __syncthreads of this
        // iteration orders those reads before the cp.async write.
    }

#pragma unroll
    for (int tm = 0; tm < 4; tm++){
        int r = bm + wm + tm*16 + g;
#pragma unroll
        for (int tn = 0; tn < 4; tn++){
            int cc = bn + wn + tn*8 + qc*2;
            *(float2*)&C[(size_t)r*ldc + cc]     = make_float2(acc[tm][tn][0], acc[tm][tn][1]);
            *(float2*)&C[(size_t)(r+8)*ldc + cc] = make_float2(acc[tm][tn][2], acc[tm][tn][3]);
        }
    }
}

// split-K partial GEMM for M: grid (6,6,KSPLIT)
__global__ __launch_bounds__(256, 2) void gemm_M_kernel(const float* __restrict__ wq,
                                                        const float* __restrict__ wk){
    int z = blockIdx.z;
    gemm_nt_tf32_body(wq + z*KCHUNK, wk + z*KCHUNK, g_Mp + (size_t)z*Dd*Dd,
                      Dd, Dd, KCHUNK);
}
// reduce partials + tf32 round
__global__ __launch_bounds__(256) void reduceM_kernel(){
    int i = blockIdx.x*256 + threadIdx.x;          // float4 index
    const int N4 = Dd*Dd/4;
    if (i >= N4) return;
    const float4* p = (const float4*)g_Mp;
    float4 a = p[i], b = p[i+N4], c = p[i+2*N4], d = p[i+3*N4];
    float4 o;
    o.x = __uint_as_float(f2tf32(a.x + b.x + c.x + d.x));
    o.y = __uint_as_float(f2tf32(a.y + b.y + c.y + d.y));
    o.z = __uint_as_float(f2tf32(a.z + b.z + c.z + d.z));
    o.w = __uint_as_float(f2tf32(a.w + b.w + c.w + d.w));
    ((float4*)g_M)[i] = o;
}

__global__ __launch_bounds__(256, 2) void gemm_Y_kernel(){
    gemm_nt_tf32_body(g_h, g_M, g_Y, Dd, Dd, Dd);  // Y[t,d] = sum_e h[t,e]*M[d,e]
}

// ---------------- bias vectors: one BLOCK per output element ----------------
__global__ __launch_bounds__(256) void biasvec_kernel(const float* __restrict__ wq,
                                                      const float* __restrict__ wk,
                                                      const float* __restrict__ bq,
                                                      const float* __restrict__ bk){
    int o = blockIdx.x;             // 0..2*Dd  (1537 blocks)
    const float* r; const float* v; float* dst;
    if (o < Dd)        { r = wq + (size_t)o*Dd;      v = bk; dst = &g_v1[o]; }
    else if (o < 2*Dd) { r = wk + (size_t)(o-Dd)*Dd; v = bq; dst = &g_v2[o-Dd]; }
    else               { r = bq;                     v = bk; dst = &g_c0; }
    int t = threadIdx.x;
    float a = r[t]*v[t] + r[t+256]*v[t+256] + r[t+512]*v[t+512];
    __shared__ float red[8];
    a = warp_sum(a);
    if ((t & 31) == 0) red[t>>5] = a;
    __syncthreads();
    if (t < 32){
        float x = (t < 8) ? red[t] : 0.f;
#pragma unroll
        for (int off = 4; off; off >>= 1) x += __shfl_xor_sync(0xffffffffu, x, off);
        if (t == 0) *dst = x;
    }
}

// ---------------- band dot products: one warp per (b,s) row ----------------
__global__ __launch_bounds__(256) void band_dots_kernel(){
    int wid  = (blockIdx.x*256 + threadIdx.x) >> 5;
    int lane = threadIdx.x & 31;
    if (wid >= BS) return;
    int s = wid & (Ss-1);
    const float* h  = g_h + (size_t)wid * Dd;
    const float* yu = g_Y + (size_t)(wid+1) * Dd;
    const float* yd = g_Y + (size_t)(wid-1) * Dd;
    bool hasU = (s < Ss-1), hasD = (s > 0);
    float au=0.f, ad=0.f, a1=0.f, a2=0.f;
#pragma unroll
    for (int j = lane*4; j < Dd; j += 128){
        float4 hv = *(const float4*)(h + j);
        float4 w1 = *(const float4*)(g_v1 + j);
        float4 w2 = *(const float4*)(g_v2 + j);
        a1 += hv.x*w1.x + hv.y*w1.y + hv.z*w1.z + hv.w*w1.w;
        a2 += hv.x*w2.x + hv.y*w2.y + hv.z*w2.z + hv.w*w2.w;
        if (hasU){ float4 y = *(const float4*)(yu + j);
                   au += hv.x*y.x + hv.y*y.y + hv.z*y.z + hv.w*y.w; }
        if (hasD){ float4 y = *(const float4*)(yd + j);
                   ad += hv.x*y.x + hv.y*y.y + hv.z*y.z + hv.w*y.w; }
    }
    au = warp_sum(au); ad = warp_sum(ad); a1 = warp_sum(a1); a2 = warp_sum(a2);
    if (lane == 0){ g_du[wid]=au; g_dd[wid]=ad; g_a1v[wid]=a1; g_a2v[wid]=a2; }
}

// ---- softmax weights for one row: returns (up_weight, down_weight) ----
__device__ __forceinline__ float2 softpair(const int* __restrict__ am, int b, int s){
    int row = b*Ss + s;
    const int* amr = am + (size_t)b*SSQ + (size_t)s*Ss;
    bool au = (s < Ss-1) && (amr[s+1] != 0);
    bool ad = (s > 0)    && (amr[s-1] != 0);
    float su = 0.f, sd = 0.f;
    if (au || ad){
        float c0 = g_c0;
        const float NEG = -3.0e38f;
        float eu = au ? (g_du[row] + g_a1v[row] + g_a2v[row+1] + c0) * (1.f/Dd) : NEG;
        float ed = ad ? (g_dd[row] + g_a1v[row] + g_a2v[row-1] + c0) * (1.f/Dd) : NEG;
        float m  = fmaxf(eu, ed);
        float xu = au ? __expf(eu - m) : 0.f;
        float xd = ad ? __expf(ed - m) : 0.f;
        float inv = 1.f / (xu + xd);
        su = xu * inv; sd = xd * inv;
    }
    return make_float2(su, sd);
}

// ------ fused band+scan: softmax, n band values, L, exclusive prefix sum ------
__global__ __launch_bounds__(1024) void scan_kernel(const int* __restrict__ am,
                                                    const float* __restrict__ prior){
    __shared__ float bufA[Ss], bufB[Ss];
    int b = blockIdx.x;
    // compute L for this batch's rows directly into smem
    for (int s = threadIdx.x; s < Ss; s += 1024){
        int row = b*Ss + s;
        float L = 0.f;
        if (s < Ss-1){
            float su = softpair(am, b, s).x;      // softn[s, s+1]
            float sd = softpair(am, b, s+1).y;    // softn[s+1, s]
            float nv = sqrtf(su * sd + 1e-9f);
            size_t base = (size_t)b*SSQ + (size_t)s*Ss;
            float p1 = prior[base + s + 1];
            float p2 = prior[base + Ss + s];
            float nsup = p1 + (1.f - p1) * nv;
            float nsub = p2 + (1.f - p2) * nv;
            g_nsup[row] = nsup; g_nsub[row] = nsub;
            L = logf(nsup + 1e-9f);
        }
        bufA[s] = L;
    }
    __syncthreads();
    float* in = bufA; float* out = bufB;
    for (int off = 1; off < Ss; off <<= 1){
        for (int i = threadIdx.x; i < Ss; i += 1024)
            out[i] = (i >= off) ? (in[i] + in[i-off]) : in[i];
        __syncthreads();
        float* t = in; in = out; out = t;
    }
    for (int i = threadIdx.x; i < Ss; i += 1024)
        g_P[b*Ss + i] = (i == 0) ? 0.f : in[i-1];
}

// ---------------- dense pass: full g and n, with band patch fused ----------------
__global__ __launch_bounds__(256) void dense_kernel(const float* __restrict__ prior,
                                                    float* __restrict__ gO,
                                                    float* __restrict__ nO){
    __shared__ float sP[Ss];
    int b  = blockIdx.x >> 8;          // 256 blocks per batch
    int r0 = (blockIdx.x & 255) * 8;   // 8 rows per block
    const float* Pb = g_P + b*Ss;
    for (int i = threadIdx.x; i < Ss; i += 256) sP[i] = Pb[i];
    __syncthreads();
    const float CC  = 3.16227766016838e-5f;  // sqrt(1e-9)
    const float OMC = 1.f - CC;
    size_t bbase = (size_t)b * SSQ;
#pragma unroll
    for (int r = 0; r < 8; r++){
        int i = r0 + r;
        float Pi = sP[i];
        size_t rbase = bbase + (size_t)i*Ss;
#pragma unroll
        for (int ccI = 0; ccI < 2; ccI++){
            int c  = threadIdx.x + ccI*256;
            int k0 = c * 4;
            float4 pr = *(const float4*)(prior + rbase + k0);
            float4 pk = *(const float4*)(sP + k0);
            float4 nv;
            nv.x = fmaf(pr.x, OMC, CC);
            nv.y = fmaf(pr.y, OMC, CC);
            nv.z = fmaf(pr.z, OMC, CC);
            nv.w = fmaf(pr.w, OMC, CC);
            float dx = (k0+0 > i) ? pk.x - Pi : Pi - pk.x;
            float dy = (k0+1 > i) ? pk.y - Pi : Pi - pk.y;
            float dz = (k0+2 > i) ? pk.z - Pi : Pi - pk.z;
            float dw = (k0+3 > i) ? pk.w - Pi : Pi - pk.w;
            float dm = fmaxf(fmaxf(dx,dy), fmaxf(dz,dw));
            float4 gv;
            if (__ballot_sync(0xffffffffu, dm > -30.f)){   // warp-uniform exp skip
                gv.x = __expf(dx) + 1e-9f;
                gv.y = __expf(dy) + 1e-9f;
                gv.z = __expf(dz) + 1e-9f;
                gv.w = __expf(dw) + 1e-9f;
            } else {
                gv.x = gv.y = gv.z = gv.w = 1e-9f;
            }
            *(float4*)(nO + rbase + k0) = nv;
            *(float4*)(gO + rbase + k0) = gv;
        }
    }
    __syncthreads();
    // fused patch: band n entries + g diagonal for this block's 8 rows
    if (threadIdx.x < 8){
        int i = r0 + threadIdx.x;
        int rowg = b*Ss + i;
        const float CC2 = 3.16227766016838e-5f;
        float pd = prior[bbase + (size_t)i*Ss + i];
        gO[bbase + (size_t)i*Ss + i] = fmaf(pd, 1.f - CC2, CC2);   // g[i,i] = n[i,i]
        if (i < Ss-1) nO[bbase + (size_t)i*Ss + i + 1] = g_nsup[rowg];
        if (i > 0)    nO[bbase + (size_t)i*Ss + i - 1] = g_nsub[rowg-1];
    }
}

// ---------------- launch ----------------
extern "C" void kernel_launch(void* const* d_in, const int* in_sizes, int n_in,
                              void* d_out, int out_size){
    const float* hidden = (const float*)d_in[0];
    const int*   amask  = (const int*)  d_in[1];
    const float* prior  = (const float*)d_in[2];
    const float* lnw    = (const float*)d_in[3];
    const float* lnb    = (const float*)d_in[4];
    const float* wq     = (const float*)d_in[5];
    const float* bq     = (const float*)d_in[6];
    const float* wk     = (const float*)d_in[7];
    const float* bk     = (const float*)d_in[8];
    float* gO = (float*)d_out;
    float* nO = gO + (size_t)Bb * SSQ;

    const int GEMM_SMEM = 2*NSTAGE*SE*sizeof(float);   // 81920 B
    cudaFuncSetAttribute(gemm_M_kernel, cudaFuncAttributeMaxDynamicSharedMemorySize, GEMM_SMEM);
    cudaFuncSetAttribute(gemm_Y_kernel, cudaFuncAttributeMaxDynamicSharedMemorySize, GEMM_SMEM);

    ln_kernel<<<BS, 256>>>(hidden, lnw, lnb);
    gemm_M_kernel<<<dim3(Dd/128, Dd/128, KSPLIT), 256, GEMM_SMEM>>>(wq, wk);
    reduceM_kernel<<<(Dd*Dd/4 + 255)/256, 256>>>();
    biasvec_kernel<<<2*Dd+1, 256>>>(wq, wk, bq, bk);
    gemm_Y_kernel<<<dim3(Dd/128, BS/128), 256, GEMM_SMEM>>>();
    band_dots_kernel<<<BS/8, 256>>>();
    scan_kernel<<<Bb, 1024>>>(amask, prior);
    dense_kernel<<<Bb*(Ss/8), 256>>>(prior, gO, nO);
}